// round 13
// baseline (speedup 1.0000x reference)
#include <cuda_runtime.h>
#include <math.h>

#define N_NODES 6144
#define F_IN    256
#define F_HID   64
#define F_OUT   32
#define NHEADS  4

// ---------------- scratch (device globals; no allocation allowed) ----------
__device__ float  g_H1[N_NODES * F_HID * NHEADS];   // layer-1 per-head features, [N][4*64]
__device__ float  g_Wp[F_IN * F_HID * NHEADS];      // repacked W_heads -> [256][256]
__device__ float  g_s1[NHEADS * N_NODES];
__device__ float  g_s2[NHEADS * N_NODES];
__device__ float  g_s2max[NHEADS];
__device__ float4 g_RowP[NHEADS * N_NODES];         // {A=exp(s1-m), B=exp(0.2 s1-m), s1, 0}
__device__ float4 g_ColP[NHEADS * N_NODES];         // {s2, C=exp(s2), D=exp(0.2 s2), 0}
__device__ float  g_OutAcc1[N_NODES * F_HID * NHEADS];
__device__ float  g_Den1[NHEADS * N_NODES];
__device__ float  g_X2[N_NODES * F_HID];
__device__ float  g_H2[N_NODES * F_OUT];
__device__ float  g_OutAcc2[N_NODES * F_OUT];
__device__ float  g_Den2[N_NODES];

// ---------------- small kernels --------------------------------------------
__global__ void zero_kernel(float* __restrict__ p, int n) {
    int i = blockIdx.x * 256 + threadIdx.x;
    if (i < n) p[i] = 0.f;
}

// W_heads [H][F_IN][F_HID] -> Wp [F_IN][H*F_HID] (col = h*64+f)
__global__ void repack_kernel(const float* __restrict__ W, float* __restrict__ Wp) {
    int idx = blockIdx.x * 256 + threadIdx.x;          // < 256*256
    int k = idx >> 8;
    int c = idx & 255;
    int h = c >> 6;
    int f = c & 63;
    Wp[idx] = W[h * (F_IN * F_HID) + k * F_HID + f];
}

// C[M][Ncol] = A[M][K] @ B[K][Ncol].  M % 64 == 0, K % 16 == 0. 256 threads.
__global__ void gemm_kernel(const float* __restrict__ A, const float* __restrict__ B,
                            float* __restrict__ C, int M, int Ncol, int K) {
    __shared__ float As[16][65];
    __shared__ float Bs[16][64];
    int tid = threadIdx.x;
    int tx = tid & 15, ty = tid >> 4;
    int rowBase = blockIdx.y * 64, colBase = blockIdx.x * 64;
    float acc[4][4] = {};
    for (int k0 = 0; k0 < K; k0 += 16) {
        for (int l = tid; l < 64 * 16; l += 256) {
            int r = l >> 4, kk = l & 15;
            As[kk][r] = A[(size_t)(rowBase + r) * K + k0 + kk];
        }
        for (int l = tid; l < 16 * 64; l += 256) {
            int kk = l >> 6, n = l & 63;
            int col = colBase + n;
            Bs[kk][n] = (col < Ncol) ? B[(size_t)(k0 + kk) * Ncol + col] : 0.f;
        }
        __syncthreads();
#pragma unroll
        for (int kk = 0; kk < 16; kk++) {
            float a[4], b[4];
#pragma unroll
            for (int i = 0; i < 4; i++) a[i] = As[kk][ty * 4 + i];
#pragma unroll
            for (int j = 0; j < 4; j++) b[j] = Bs[kk][tx * 4 + j];
#pragma unroll
            for (int i = 0; i < 4; i++)
#pragma unroll
                for (int j = 0; j < 4; j++) acc[i][j] = fmaf(a[i], b[j], acc[i][j]);
        }
        __syncthreads();
    }
#pragma unroll
    for (int i = 0; i < 4; i++) {
        int row = rowBase + ty * 4 + i;
#pragma unroll
        for (int j = 0; j < 4; j++) {
            int col = colBase + tx * 4 + j;
            if (col < Ncol) C[(size_t)row * Ncol + col] = acc[i][j];
        }
    }
}

// s1[h*N+i] = H[i, h*F:(h+1)*F] . a[h][0:F];  s2 with a[h][F:2F]. One warp per (h,i).
__global__ void score_kernel(const float* __restrict__ H, const float* __restrict__ a,
                             float* __restrict__ s1o, float* __restrict__ s2o,
                             int N, int F, int heads) {
    int gt = blockIdx.x * blockDim.x + threadIdx.x;
    int w = gt >> 5, lane = gt & 31;
    if (w >= N * heads) return;
    int h = w / N, i = w - h * N;
    const float* hr = H + (size_t)i * F * heads + h * F;
    const float* a1 = a + h * 2 * F;
    const float* a2 = a1 + F;
    float p1 = 0.f, p2 = 0.f;
    for (int f = lane; f < F; f += 32) {
        float hv = hr[f];
        p1 = fmaf(hv, a1[f], p1);
        p2 = fmaf(hv, a2[f], p2);
    }
#pragma unroll
    for (int o = 16; o; o >>= 1) {
        p1 += __shfl_down_sync(0xffffffffu, p1, o);
        p2 += __shfl_down_sync(0xffffffffu, p2, o);
    }
    if (lane == 0) { s1o[w] = p1; s2o[w] = p2; }
}

__global__ void s2max_kernel(const float* __restrict__ s2, float* __restrict__ out, int N) {
    __shared__ float sm[256];
    const float* p = s2 + (size_t)blockIdx.x * N;
    float m = -1e30f;
    for (int i = threadIdx.x; i < N; i += 256) m = fmaxf(m, p[i]);
    sm[threadIdx.x] = m;
    __syncthreads();
    for (int s = 128; s; s >>= 1) {
        if (threadIdx.x < s) sm[threadIdx.x] = fmaxf(sm[threadIdx.x], sm[threadIdx.x + s]);
        __syncthreads();
    }
    if (threadIdx.x == 0) out[blockIdx.x] = sm[0];
}

__global__ void param_kernel(const float* __restrict__ s1, const float* __restrict__ s2,
                             const float* __restrict__ s2max,
                             float4* __restrict__ RowP, float4* __restrict__ ColP,
                             int N, int heads) {
    int idx = blockIdx.x * 256 + threadIdx.x;
    if (idx >= N * heads) return;
    int h = idx / N;
    float sv1 = s1[idx], sv2 = s2[idx];
    float t = sv1 + s2max[h];
    float m = (t > 0.f) ? t : 0.2f * t;                 // upper bound of row max (shift-safe)
    RowP[idx] = make_float4(expf(sv1 - m), expf(0.2f * sv1 - m), sv1, 0.f);
    ColP[idx] = make_float4(sv2, expf(sv2), expf(0.2f * sv2), 0.f);
}

// ---------------- heavy masked-attention aggregate --------------------------
// OutAcc[i][f] += sum_j w(h(f),i,j) * H[j][f];  Den[h][i] += sum_j w(h,i,j)
// w(h,i,j) = adj[i][j] ? ((s1+s2>=0) ? A_i*C_j : B_i*D_j) : 0   (all per head h)
template <int BM, int BJ, int HEADS, int F, int RPT, int FPT>
__global__ void __launch_bounds__(256, 2)
heavy_kernel(const int* __restrict__ adj, const float* __restrict__ H,
             const float4* __restrict__ RowP, const float4* __restrict__ ColP,
             float* __restrict__ OutAcc, float* __restrict__ Den,
             int N, int jPerBlock) {
    constexpr int FPH    = F / HEADS;
    constexpr int FG     = F / FPT;
    constexpr int PAIRS  = HEADS * BM;
    constexpr int NSLICE = 256 / PAIRS;
    constexpr int JS     = BJ / NSLICE;
    static_assert((BM / RPT) * FG == 256, "thread map");
    static_assert(256 % PAIRS == 0 && BJ % NSLICE == 0, "build map");

    extern __shared__ float smem[];
    float*  Hs   = smem;                                 // [BJ][F]
    float*  Ws   = Hs + BJ * F;                          // [BJ][HEADS*BM]
    int*    adjS = (int*)(Ws + BJ * PAIRS);              // [BM][BJ+1] (pad kills conflicts)
    float4* colS = (float4*)(adjS + BM * (BJ + 1));      // [BJ][HEADS]

    int tid = threadIdx.x;
    int rowBase = blockIdx.x * BM;
    int jBase0  = blockIdx.y * jPerBlock;

    // GEMM-phase mapping
    int rg = tid / FG, fg = tid % FG;
    int r0 = rg * RPT, f0 = fg * FPT;
    int headF = f0 / FPH;

    // build-phase mapping
    int p = tid % PAIRS;
    int slice = tid / PAIRS;
    int h_b = p / BM, r_b = p % BM;
    float4 rp = RowP[(size_t)h_b * N + rowBase + r_b];
    float denom_acc = 0.f;

    float acc[RPT][FPT];
#pragma unroll
    for (int r = 0; r < RPT; r++)
#pragma unroll
        for (int f = 0; f < FPT; f++) acc[r][f] = 0.f;

    for (int jc = 0; jc < jPerBlock; jc += BJ) {
        int jBase = jBase0 + jc;
        // stage adj tile (coalesced)
        for (int l = tid; l < BM * BJ; l += 256) {
            int r = l / BJ, j = l % BJ;
            adjS[r * (BJ + 1) + j] = adj[(size_t)(rowBase + r) * N + jBase + j];
        }
        // stage H chunk (rows jBase..jBase+BJ are contiguous)
        for (int l = tid; l < BJ * F / 4; l += 256)
            ((float4*)Hs)[l] = ((const float4*)H)[(size_t)jBase * (F / 4) + l];
        // stage column params
        for (int l = tid; l < BJ * HEADS; l += 256) {
            int j = l / HEADS, h = l % HEADS;
            colS[l] = ColP[(size_t)h * N + jBase + j];
        }
        __syncthreads();

        // build weight tile + accumulate denominators
#pragma unroll
        for (int jj = 0; jj < JS; jj++) {
            int j = slice * JS + jj;
            float4 cp = colS[j * HEADS + h_b];
            float t = rp.z + cp.x;                        // s1 + s2
            float w = (t >= 0.f) ? (rp.x * cp.y) : (rp.y * cp.z);
            w = adjS[r_b * (BJ + 1) + j] ? w : 0.f;
            Ws[j * PAIRS + h_b * BM + r_b] = w;
            denom_acc += w;
        }
        __syncthreads();

        // outer-product GEMM: acc[r][f] += w[r] * h[f]
#pragma unroll 4
        for (int j = 0; j < BJ; j++) {
            float hv[FPT];
#pragma unroll
            for (int v = 0; v < FPT / 4; v++)
                *(float4*)(hv + 4 * v) = *(const float4*)(Hs + j * F + f0 + 4 * v);
            float wv[RPT];
            if constexpr (RPT % 4 == 0) {
#pragma unroll
                for (int v = 0; v < RPT / 4; v++)
                    *(float4*)(wv + 4 * v) = *(const float4*)(Ws + j * PAIRS + headF * BM + r0 + 4 * v);
            } else {
#pragma unroll
                for (int r = 0; r < RPT; r++)
                    wv[r] = Ws[j * PAIRS + headF * BM + r0 + r];
            }
#pragma unroll
            for (int r = 0; r < RPT; r++)
#pragma unroll
                for (int f = 0; f < FPT; f++)
                    acc[r][f] = fmaf(wv[r], hv[f], acc[r][f]);
        }
        __syncthreads();
    }

#pragma unroll
    for (int r = 0; r < RPT; r++)
#pragma unroll
        for (int f = 0; f < FPT; f++)
            atomicAdd(&OutAcc[(size_t)(rowBase + r0 + r) * F + f0 + f], acc[r][f]);
    atomicAdd(&Den[(size_t)h_b * N + rowBase + r_b], denom_acc);
}

// ---------------- epilogues -------------------------------------------------
__device__ __forceinline__ float elu_f(float v) { return v > 0.f ? v : expm1f(v); }

__global__ void epilogue1_kernel(const float* __restrict__ OutAcc, const float* __restrict__ Den,
                                 float* __restrict__ X2) {
    int idx = blockIdx.x * 256 + threadIdx.x;
    if (idx >= N_NODES * F_HID) return;
    int i = idx / F_HID, f = idx % F_HID;
    float s = 0.f;
#pragma unroll
    for (int h = 0; h < NHEADS; h++) {
        float v = OutAcc[(size_t)i * (NHEADS * F_HID) + h * F_HID + f] / Den[(size_t)h * N_NODES + i];
        s += elu_f(v);
    }
    X2[idx] = s * 0.25f;
}

__global__ void epilogue2_kernel(const float* __restrict__ OutAcc, const float* __restrict__ Den,
                                 float* __restrict__ out) {
    int idx = blockIdx.x * 256 + threadIdx.x;
    if (idx >= N_NODES * F_OUT) return;
    int i = idx / F_OUT;
    float v = OutAcc[idx] / Den[i];
    out[idx] = elu_f(v);
}

// ---------------- launch ----------------------------------------------------
extern "C" void kernel_launch(void* const* d_in, const int* in_sizes, int n_in,
                              void* d_out, int out_size) {
    const float* x       = (const float*)d_in[0];
    const int*   adj     = (const int*)  d_in[1];
    const float* W_heads = (const float*)d_in[2];
    const float* a_heads = (const float*)d_in[3];
    const float* W_out   = (const float*)d_in[4];
    const float* a_out   = (const float*)d_in[5];
    float* out = (float*)d_out;
    const int N = N_NODES;

    float  *H1, *Wp, *s1, *s2, *s2m, *OutAcc1, *Den1, *X2, *H2, *OutAcc2, *Den2;
    float4 *RowP, *ColP;
    cudaGetSymbolAddress((void**)&H1,      g_H1);
    cudaGetSymbolAddress((void**)&Wp,      g_Wp);
    cudaGetSymbolAddress((void**)&s1,      g_s1);
    cudaGetSymbolAddress((void**)&s2,      g_s2);
    cudaGetSymbolAddress((void**)&s2m,     g_s2max);
    cudaGetSymbolAddress((void**)&RowP,    g_RowP);
    cudaGetSymbolAddress((void**)&ColP,    g_ColP);
    cudaGetSymbolAddress((void**)&OutAcc1, g_OutAcc1);
    cudaGetSymbolAddress((void**)&Den1,    g_Den1);
    cudaGetSymbolAddress((void**)&X2,      g_X2);
    cudaGetSymbolAddress((void**)&H2,      g_H2);
    cudaGetSymbolAddress((void**)&OutAcc2, g_OutAcc2);
    cudaGetSymbolAddress((void**)&Den2,    g_Den2);

    const int SMEM1 = (32 * 256 + 32 * 128) * 4 + 32 * 33 * 4 + 32 * 4 * 16;  // 55424
    const int SMEM2 = (32 * 32 + 32 * 32) * 4 + 32 * 33 * 4 + 32 * 1 * 16;    // 12928
    cudaFuncSetAttribute(heavy_kernel<32, 32, 4, 256, 4, 8>,
                         cudaFuncAttributeMaxDynamicSharedMemorySize, SMEM1);
    cudaFuncSetAttribute(heavy_kernel<32, 32, 1, 32, 1, 4>,
                         cudaFuncAttributeMaxDynamicSharedMemorySize, SMEM2);

    // zero accumulators (must happen every call: atomics accumulate)
    zero_kernel<<<(N * 256 + 255) / 256, 256>>>(OutAcc1, N * 256);
    zero_kernel<<<(4 * N + 255) / 256, 256>>>(Den1, 4 * N);
    zero_kernel<<<(N * 32 + 255) / 256, 256>>>(OutAcc2, N * 32);
    zero_kernel<<<(N + 255) / 256, 256>>>(Den2, N);

    // ---- layer 1 ----
    repack_kernel<<<256, 256>>>(W_heads, Wp);
    gemm_kernel<<<dim3(4, 96), 256>>>(x, Wp, H1, N, 256, 256);
    score_kernel<<<(N * 4 * 32 + 255) / 256, 256>>>(H1, a_heads, s1, s2, N, 64, 4);
    s2max_kernel<<<4, 256>>>(s2, s2m, N);
    param_kernel<<<(N * 4 + 255) / 256, 256>>>(s1, s2, s2m, RowP, ColP, N, 4);
    heavy_kernel<32, 32, 4, 256, 4, 8><<<dim3(192, 6), 256, SMEM1>>>(
        adj, H1, RowP, ColP, OutAcc1, Den1, N, N / 6);
    epilogue1_kernel<<<(N * 64 + 255) / 256, 256>>>(OutAcc1, Den1, X2);

    // ---- layer 2 ----
    gemm_kernel<<<dim3(1, 96), 256>>>(X2, W_out, H2, N, 32, 64);
    score_kernel<<<(N * 32 + 255) / 256, 256>>>(H2, a_out, s1, s2, N, 32, 1);
    s2max_kernel<<<1, 256>>>(s2, s2m, N);
    param_kernel<<<(N + 255) / 256, 256>>>(s1, s2, s2m, RowP, ColP, N, 1);
    heavy_kernel<32, 32, 1, 32, 1, 4><<<dim3(192, 6), 256, SMEM2>>>(
        adj, H2, RowP, ColP, OutAcc2, Den2, N, N / 6);
    epilogue2_kernel<<<(N * 32 + 255) / 256, 256>>>(OutAcc2, Den2, out);
}

// round 14
// speedup vs baseline: 1.0007x; 1.0007x over previous
#include <cuda_runtime.h>
#include <math.h>

#define N_NODES 6144
#define F_IN    256
#define F_HID   64
#define F_OUT   32
#define NHEADS  4

// ---------------- scratch (device globals; no allocation allowed) ----------
__device__ float  g_H1[N_NODES * F_HID * NHEADS];   // layer-1 per-head features, [N][4*64]
__device__ float  g_Wp[F_IN * F_HID * NHEADS];      // repacked W_heads -> [256][256]
__device__ float  g_s1[NHEADS * N_NODES];
__device__ float  g_s2[NHEADS * N_NODES];
__device__ float  g_s2max[NHEADS];
__device__ float4 g_RowP[NHEADS * N_NODES];         // {A=exp(s1-m), B=exp(0.2 s1-m), s1, 0}
__device__ float4 g_ColP[NHEADS * N_NODES];         // {s2, C=exp(s2), D=exp(0.2 s2), 0}
__device__ float  g_OutAcc1[N_NODES * F_HID * NHEADS];
__device__ float  g_Den1[NHEADS * N_NODES];
__device__ float  g_X2[N_NODES * F_HID];
__device__ float  g_H2[N_NODES * F_OUT];
__device__ float  g_OutAcc2[N_NODES * F_OUT];
__device__ float  g_Den2[N_NODES];

// ---------------- small kernels --------------------------------------------
__global__ void zero_kernel(float* __restrict__ p, int n) {
    int i = blockIdx.x * 256 + threadIdx.x;
    if (i < n) p[i] = 0.f;
}

// W_heads [H][F_IN][F_HID] -> Wp [F_IN][H*F_HID] (col = h*64+f)
__global__ void repack_kernel(const float* __restrict__ W, float* __restrict__ Wp) {
    int idx = blockIdx.x * 256 + threadIdx.x;          // < 256*256
    int k = idx >> 8;
    int c = idx & 255;
    int h = c >> 6;
    int f = c & 63;
    Wp[idx] = W[h * (F_IN * F_HID) + k * F_HID + f];
}

// C[M][Ncol] = A[M][K] @ B[K][Ncol].  M % 64 == 0, K % 16 == 0. 256 threads.
__global__ void gemm_kernel(const float* __restrict__ A, const float* __restrict__ B,
                            float* __restrict__ C, int M, int Ncol, int K) {
    __shared__ float As[16][65];
    __shared__ float Bs[16][64];
    int tid = threadIdx.x;
    int tx = tid & 15, ty = tid >> 4;
    int rowBase = blockIdx.y * 64, colBase = blockIdx.x * 64;
    float acc[4][4] = {};
    for (int k0 = 0; k0 < K; k0 += 16) {
        for (int l = tid; l < 64 * 16; l += 256) {
            int r = l >> 4, kk = l & 15;
            As[kk][r] = A[(size_t)(rowBase + r) * K + k0 + kk];
        }
        for (int l = tid; l < 16 * 64; l += 256) {
            int kk = l >> 6, n = l & 63;
            int col = colBase + n;
            Bs[kk][n] = (col < Ncol) ? B[(size_t)(k0 + kk) * Ncol + col] : 0.f;
        }
        __syncthreads();
#pragma unroll
        for (int kk = 0; kk < 16; kk++) {
            float a[4], b[4];
#pragma unroll
            for (int i = 0; i < 4; i++) a[i] = As[kk][ty * 4 + i];
#pragma unroll
            for (int j = 0; j < 4; j++) b[j] = Bs[kk][tx * 4 + j];
#pragma unroll
            for (int i = 0; i < 4; i++)
#pragma unroll
                for (int j = 0; j < 4; j++) acc[i][j] = fmaf(a[i], b[j], acc[i][j]);
        }
        __syncthreads();
    }
#pragma unroll
    for (int i = 0; i < 4; i++) {
        int row = rowBase + ty * 4 + i;
#pragma unroll
        for (int j = 0; j < 4; j++) {
            int col = colBase + tx * 4 + j;
            if (col < Ncol) C[(size_t)row * Ncol + col] = acc[i][j];
        }
    }
}

// s1[h*N+i] = H[i, h*F:(h+1)*F] . a[h][0:F];  s2 with a[h][F:2F]. One warp per (h,i).
__global__ void score_kernel(const float* __restrict__ H, const float* __restrict__ a,
                             float* __restrict__ s1o, float* __restrict__ s2o,
                             int N, int F, int heads) {
    int gt = blockIdx.x * blockDim.x + threadIdx.x;
    int w = gt >> 5, lane = gt & 31;
    if (w >= N * heads) return;
    int h = w / N, i = w - h * N;
    const float* hr = H + (size_t)i * F * heads + h * F;
    const float* a1 = a + h * 2 * F;
    const float* a2 = a1 + F;
    float p1 = 0.f, p2 = 0.f;
    for (int f = lane; f < F; f += 32) {
        float hv = hr[f];
        p1 = fmaf(hv, a1[f], p1);
        p2 = fmaf(hv, a2[f], p2);
    }
#pragma unroll
    for (int o = 16; o; o >>= 1) {
        p1 += __shfl_down_sync(0xffffffffu, p1, o);
        p2 += __shfl_down_sync(0xffffffffu, p2, o);
    }
    if (lane == 0) { s1o[w] = p1; s2o[w] = p2; }
}

__global__ void s2max_kernel(const float* __restrict__ s2, float* __restrict__ out, int N) {
    __shared__ float sm[256];
    const float* p = s2 + (size_t)blockIdx.x * N;
    float m = -1e30f;
    for (int i = threadIdx.x; i < N; i += 256) m = fmaxf(m, p[i]);
    sm[threadIdx.x] = m;
    __syncthreads();
    for (int s = 128; s; s >>= 1) {
        if (threadIdx.x < s) sm[threadIdx.x] = fmaxf(sm[threadIdx.x], sm[threadIdx.x + s]);
        __syncthreads();
    }
    if (threadIdx.x == 0) out[blockIdx.x] = sm[0];
}

__global__ void param_kernel(const float* __restrict__ s1, const float* __restrict__ s2,
                             const float* __restrict__ s2max,
                             float4* __restrict__ RowP, float4* __restrict__ ColP,
                             int N, int heads) {
    int idx = blockIdx.x * 256 + threadIdx.x;
    if (idx >= N * heads) return;
    int h = idx / N;
    float sv1 = s1[idx], sv2 = s2[idx];
    float t = sv1 + s2max[h];
    float m = (t > 0.f) ? t : 0.2f * t;                 // upper bound of row max (shift-safe)
    RowP[idx] = make_float4(expf(sv1 - m), expf(0.2f * sv1 - m), sv1, 0.f);
    ColP[idx] = make_float4(sv2, expf(sv2), expf(0.2f * sv2), 0.f);
}

// ---------------- heavy masked-attention aggregate --------------------------
// OutAcc[i][f] += sum_j w(h(f),i,j) * H[j][f];  Den[h][i] += sum_j w(h,i,j)
// w(h,i,j) = adj[i][j] ? ((s1+s2>=0) ? A_i*C_j : B_i*D_j) : 0   (all per head h)
template <int BM, int BJ, int HEADS, int F, int RPT, int FPT>
__global__ void __launch_bounds__(256, 2)
heavy_kernel(const int* __restrict__ adj, const float* __restrict__ H,
             const float4* __restrict__ RowP, const float4* __restrict__ ColP,
             float* __restrict__ OutAcc, float* __restrict__ Den,
             int N, int jPerBlock) {
    constexpr int FPH    = F / HEADS;
    constexpr int FG     = F / FPT;
    constexpr int PAIRS  = HEADS * BM;
    constexpr int NSLICE = 256 / PAIRS;
    constexpr int JS     = BJ / NSLICE;
    static_assert((BM / RPT) * FG == 256, "thread map");
    static_assert(256 % PAIRS == 0 && BJ % NSLICE == 0, "build map");

    extern __shared__ float smem[];
    float*  Hs   = smem;                                 // [BJ][F]
    float*  Ws   = Hs + BJ * F;                          // [BJ][HEADS*BM]
    int*    adjS = (int*)(Ws + BJ * PAIRS);              // [BM][BJ+1] (pad kills conflicts)
    float4* colS = (float4*)(adjS + BM * (BJ + 1));      // [BJ][HEADS]

    int tid = threadIdx.x;
    int rowBase = blockIdx.x * BM;
    int jBase0  = blockIdx.y * jPerBlock;

    // GEMM-phase mapping
    int rg = tid / FG, fg = tid % FG;
    int r0 = rg * RPT, f0 = fg * FPT;
    int headF = f0 / FPH;

    // build-phase mapping
    int p = tid % PAIRS;
    int slice = tid / PAIRS;
    int h_b = p / BM, r_b = p % BM;
    float4 rp = RowP[(size_t)h_b * N + rowBase + r_b];
    float denom_acc = 0.f;

    float acc[RPT][FPT];
#pragma unroll
    for (int r = 0; r < RPT; r++)
#pragma unroll
        for (int f = 0; f < FPT; f++) acc[r][f] = 0.f;

    for (int jc = 0; jc < jPerBlock; jc += BJ) {
        int jBase = jBase0 + jc;
        // stage adj tile (coalesced)
        for (int l = tid; l < BM * BJ; l += 256) {
            int r = l / BJ, j = l % BJ;
            adjS[r * (BJ + 1) + j] = adj[(size_t)(rowBase + r) * N + jBase + j];
        }
        // stage H chunk (rows jBase..jBase+BJ are contiguous)
        for (int l = tid; l < BJ * F / 4; l += 256)
            ((float4*)Hs)[l] = ((const float4*)H)[(size_t)jBase * (F / 4) + l];
        // stage column params
        for (int l = tid; l < BJ * HEADS; l += 256) {
            int j = l / HEADS, h = l % HEADS;
            colS[l] = ColP[(size_t)h * N + jBase + j];
        }
        __syncthreads();

        // build weight tile + accumulate denominators
#pragma unroll
        for (int jj = 0; jj < JS; jj++) {
            int j = slice * JS + jj;
            float4 cp = colS[j * HEADS + h_b];
            float t = rp.z + cp.x;                        // s1 + s2
            float w = (t >= 0.f) ? (rp.x * cp.y) : (rp.y * cp.z);
            w = adjS[r_b * (BJ + 1) + j] ? w : 0.f;
            Ws[j * PAIRS + h_b * BM + r_b] = w;
            denom_acc += w;
        }
        __syncthreads();

        // outer-product GEMM: acc[r][f] += w[r] * h[f]
#pragma unroll 4
        for (int j = 0; j < BJ; j++) {
            float hv[FPT];
#pragma unroll
            for (int v = 0; v < FPT / 4; v++)
                *(float4*)(hv + 4 * v) = *(const float4*)(Hs + j * F + f0 + 4 * v);
            float wv[RPT];
            if constexpr (RPT % 4 == 0) {
#pragma unroll
                for (int v = 0; v < RPT / 4; v++)
                    *(float4*)(wv + 4 * v) = *(const float4*)(Ws + j * PAIRS + headF * BM + r0 + 4 * v);
            } else {
#pragma unroll
                for (int r = 0; r < RPT; r++)
                    wv[r] = Ws[j * PAIRS + headF * BM + r0 + r];
            }
#pragma unroll
            for (int r = 0; r < RPT; r++)
#pragma unroll
                for (int f = 0; f < FPT; f++)
                    acc[r][f] = fmaf(wv[r], hv[f], acc[r][f]);
        }
        __syncthreads();
    }

#pragma unroll
    for (int r = 0; r < RPT; r++)
#pragma unroll
        for (int f = 0; f < FPT; f++)
            atomicAdd(&OutAcc[(size_t)(rowBase + r0 + r) * F + f0 + f], acc[r][f]);
    atomicAdd(&Den[(size_t)h_b * N + rowBase + r_b], denom_acc);
}

// ---------------- epilogues -------------------------------------------------
__device__ __forceinline__ float elu_f(float v) { return v > 0.f ? v : expm1f(v); }

__global__ void epilogue1_kernel(const float* __restrict__ OutAcc, const float* __restrict__ Den,
                                 float* __restrict__ X2) {
    int idx = blockIdx.x * 256 + threadIdx.x;
    if (idx >= N_NODES * F_HID) return;
    int i = idx / F_HID, f = idx % F_HID;
    float s = 0.f;
#pragma unroll
    for (int h = 0; h < NHEADS; h++) {
        float v = OutAcc[(size_t)i * (NHEADS * F_HID) + h * F_HID + f] / Den[(size_t)h * N_NODES + i];
        s += elu_f(v);
    }
    X2[idx] = s * 0.25f;
}

__global__ void epilogue2_kernel(const float* __restrict__ OutAcc, const float* __restrict__ Den,
                                 float* __restrict__ out) {
    int idx = blockIdx.x * 256 + threadIdx.x;
    if (idx >= N_NODES * F_OUT) return;
    int i = idx / F_OUT;
    float v = OutAcc[idx] / Den[i];
    out[idx] = elu_f(v);
}

// ---------------- launch ----------------------------------------------------
extern "C" void kernel_launch(void* const* d_in, const int* in_sizes, int n_in,
                              void* d_out, int out_size) {
    const float* x       = (const float*)d_in[0];
    const int*   adj     = (const int*)  d_in[1];
    const float* W_heads = (const float*)d_in[2];
    const float* a_heads = (const float*)d_in[3];
    const float* W_out   = (const float*)d_in[4];
    const float* a_out   = (const float*)d_in[5];
    float* out = (float*)d_out;
    const int N = N_NODES;

    float  *H1, *Wp, *s1, *s2, *s2m, *OutAcc1, *Den1, *X2, *H2, *OutAcc2, *Den2;
    float4 *RowP, *ColP;
    cudaGetSymbolAddress((void**)&H1,      g_H1);
    cudaGetSymbolAddress((void**)&Wp,      g_Wp);
    cudaGetSymbolAddress((void**)&s1,      g_s1);
    cudaGetSymbolAddress((void**)&s2,      g_s2);
    cudaGetSymbolAddress((void**)&s2m,     g_s2max);
    cudaGetSymbolAddress((void**)&RowP,    g_RowP);
    cudaGetSymbolAddress((void**)&ColP,    g_ColP);
    cudaGetSymbolAddress((void**)&OutAcc1, g_OutAcc1);
    cudaGetSymbolAddress((void**)&Den1,    g_Den1);
    cudaGetSymbolAddress((void**)&X2,      g_X2);
    cudaGetSymbolAddress((void**)&H2,      g_H2);
    cudaGetSymbolAddress((void**)&OutAcc2, g_OutAcc2);
    cudaGetSymbolAddress((void**)&Den2,    g_Den2);

    const int SMEM1 = (32 * 256 + 32 * 128) * 4 + 32 * 33 * 4 + 32 * 4 * 16;  // 55424
    const int SMEM2 = (32 * 32 + 32 * 32) * 4 + 32 * 33 * 4 + 32 * 1 * 16;    // 12928
    cudaFuncSetAttribute(heavy_kernel<32, 32, 4, 256, 4, 8>,
                         cudaFuncAttributeMaxDynamicSharedMemorySize, SMEM1);
    cudaFuncSetAttribute(heavy_kernel<32, 32, 1, 32, 1, 4>,
                         cudaFuncAttributeMaxDynamicSharedMemorySize, SMEM2);

    // zero accumulators (must happen every call: atomics accumulate)
    zero_kernel<<<(N * 256 + 255) / 256, 256>>>(OutAcc1, N * 256);
    zero_kernel<<<(4 * N + 255) / 256, 256>>>(Den1, 4 * N);
    zero_kernel<<<(N * 32 + 255) / 256, 256>>>(OutAcc2, N * 32);
    zero_kernel<<<(N + 255) / 256, 256>>>(Den2, N);

    // ---- layer 1 ----
    repack_kernel<<<256, 256>>>(W_heads, Wp);
    gemm_kernel<<<dim3(4, 96), 256>>>(x, Wp, H1, N, 256, 256);
    score_kernel<<<(N * 4 * 32 + 255) / 256, 256>>>(H1, a_heads, s1, s2, N, 64, 4);
    s2max_kernel<<<4, 256>>>(s2, s2m, N);
    param_kernel<<<(N * 4 + 255) / 256, 256>>>(s1, s2, s2m, RowP, ColP, N, 4);
    heavy_kernel<32, 32, 4, 256, 4, 8><<<dim3(192, 6), 256, SMEM1>>>(
        adj, H1, RowP, ColP, OutAcc1, Den1, N, N / 6);
    epilogue1_kernel<<<(N * 64 + 255) / 256, 256>>>(OutAcc1, Den1, X2);

    // ---- layer 2 ----
    gemm_kernel<<<dim3(1, 96), 256>>>(X2, W_out, H2, N, 32, 64);
    score_kernel<<<(N * 32 + 255) / 256, 256>>>(H2, a_out, s1, s2, N, 32, 1);
    s2max_kernel<<<1, 256>>>(s2, s2m, N);
    param_kernel<<<(N + 255) / 256, 256>>>(s1, s2, s2m, RowP, ColP, N, 1);
    heavy_kernel<32, 32, 1, 32, 1, 4><<<dim3(192, 6), 256, SMEM2>>>(
        adj, H2, RowP, ColP, OutAcc2, Den2, N, N / 6);
    epilogue2_kernel<<<(N * 32 + 255) / 256, 256>>>(OutAcc2, Den2, out);
}